// round 14
// baseline (speedup 1.0000x reference)
#include <cuda_runtime.h>
#include <cuda_fp16.h>
#include <math.h>
#include <stdint.h>

// Problem constants: B=2, S=1024 -> T=2048 tokens; D=768; E=8 experts; DFF=3072; top-2.
#define T    2048
#define D    768
#define E    8
#define DFF  3072

// GEMM tiling: 128x256 CTA tile, 256 threads (8 warps, 2x4), 64x64 warp tiles,
// BK=64 (4 sub-k16 per sync), fp16 mma.sync + ldmatrix, 3-stage cp.async,
// software-pipelined fragments. Single persistent kernel runs BOTH GEMMs with
// fine-grained cross-GEMM dependency tracking (GEMM2 overlaps GEMM1's tail).
#define BM 128
#define BN 256
#define BK 64
#define SA 72                       // smem row stride (halves): 64 + 8 pad
#define STAGES 3
#define STG_ROWS (BM + BN)          // 384 rows (A then B) per stage
#define STG_BYTES (STG_ROWS * SA * 2)   // 55296 B per stage
#define SMEM_TOT (STAGES * STG_BYTES)   // 165888 B
#define SPLITK 4
#define NSM 148

// tile bookkeeping: both GEMMs have NKT = 12 (768 / 64)
#define NKT  12
#define GX1  (DFF / BN)             // 12 n-tiles (GEMM1)
#define GX2  (D / BN)               // 3  n-tiles (GEMM2)
#define GY   (T / BM)               // 16 m-tiles
#define NT1  (GX1 * GY * E)         // 1536 GEMM1 tiles
#define NT2  (GX2 * GY * E * SPLITK)// 1536 GEMM2 tiles
#define NTALL (NT1 + NT2)
#define DEP_TARGET (3 * GY)         // 48 GEMM1 tiles per (e, sK) dependency

// ---------------------------------------------------------------------------
// Device scratch
// ---------------------------------------------------------------------------
__device__ int    g_cnt[E];
__device__ int    g_tok[E * T];
__device__ int    g_rowof[T * 2];
__device__ float  g_w[T * 2];
__device__ int    g_q;                            // persistent tile queue
__device__ int    g_done[E * SPLITK];             // GEMM1->GEMM2 dep counters
__device__ __half g_xh[T * D];                    // x in fp16
__device__ __half g_W1h[(size_t)E * DFF * D];     // W1 in fp16
__device__ __half g_W2h[(size_t)E * D * DFF];     // W2 in fp16
__device__ __half g_Hh[(size_t)E * T * DFF];      // hidden acts, fp16
__device__ float  g_Y[SPLITK][E * T * D];         // split-K partial outputs

__global__ void reset_kernel() {
    if (threadIdx.x < E) g_cnt[threadIdx.x] = 0;
    if (threadIdx.x == 0) g_q = 0;
    if (threadIdx.x < E * SPLITK) g_done[threadIdx.x] = 0;
}

// ---------------------------------------------------------------------------
// fp32 -> fp16 conversion for x, W1, W2 in one launch (8 elems / thread)
// ---------------------------------------------------------------------------
__device__ __forceinline__ uint4 pack8(float4 a, float4 b) {
    __half2 h0 = __floats2half2_rn(a.x, a.y);
    __half2 h1 = __floats2half2_rn(a.z, a.w);
    __half2 h2 = __floats2half2_rn(b.x, b.y);
    __half2 h3 = __floats2half2_rn(b.z, b.w);
    uint4 u;
    u.x = *reinterpret_cast<uint32_t*>(&h0);
    u.y = *reinterpret_cast<uint32_t*>(&h1);
    u.z = *reinterpret_cast<uint32_t*>(&h2);
    u.w = *reinterpret_cast<uint32_t*>(&h3);
    return u;
}

__global__ void cvt3_kernel(const float* __restrict__ x,
                            const float* __restrict__ W1,
                            const float* __restrict__ W2,
                            __half* __restrict__ xh,
                            __half* __restrict__ w1h,
                            __half* __restrict__ w2h,
                            int nx8, int nw8)
{
    const int i = blockIdx.x * blockDim.x + threadIdx.x;
    const float* src; __half* dst; int j;
    if (i < nx8)            { src = x;  dst = xh;  j = i; }
    else if (i < nx8 + nw8) { src = W1; dst = w1h; j = i - nx8; }
    else if (i < nx8 + 2 * nw8) { src = W2; dst = w2h; j = i - nx8 - nw8; }
    else return;
    const float4 a = reinterpret_cast<const float4*>(src)[2 * j];
    const float4 b = reinterpret_cast<const float4*>(src)[2 * j + 1];
    reinterpret_cast<uint4*>(dst)[j] = pack8(a, b);
}

// ---------------------------------------------------------------------------
// Router: one warp per token, noisy top-2 gating + atomic per-expert
// compaction. Row values are position-invariant -> deterministic output.
// ---------------------------------------------------------------------------
__global__ void router_kernel(const float* __restrict__ x,
                              const float* __restrict__ noise,
                              const float* __restrict__ Wg,
                              const float* __restrict__ bg,
                              const float* __restrict__ Wn,
                              const float* __restrict__ bn)
{
    const int warp = (blockIdx.x * blockDim.x + threadIdx.x) >> 5;
    const int lane = threadIdx.x & 31;
    if (warp >= T) return;

    const float* xr = x + (size_t)warp * D;
    float xv[D / 32];
    #pragma unroll
    for (int i = 0; i < D / 32; i++) xv[i] = xr[lane + 32 * i];

    float nz[E];
    #pragma unroll
    for (int e = 0; e < E; e++) {
        const float* g  = Wg + e * D;
        const float* nw = Wn + e * D;
        float s1 = 0.f, s2 = 0.f;
        #pragma unroll
        for (int i = 0; i < D / 32; i++) {
            const float xi = xv[i];
            s1 = fmaf(xi, g[lane + 32 * i], s1);
            s2 = fmaf(xi, nw[lane + 32 * i], s2);
        }
        #pragma unroll
        for (int off = 16; off; off >>= 1) {
            s1 += __shfl_xor_sync(0xffffffffu, s1, off);
            s2 += __shfl_xor_sync(0xffffffffu, s2, off);
        }
        const float logit = s1 + bg[e];
        const float nlog  = s2 + bn[e];
        const float sp = fmaxf(nlog, 0.f) + log1pf(expf(-fabsf(nlog)));
        nz[e] = logit + noise[warp * E + e] * sp;
    }

    if (lane == 0) {
        int i0 = 0; float v0 = nz[0];
        #pragma unroll
        for (int e = 1; e < E; e++) if (nz[e] > v0) { v0 = nz[e]; i0 = e; }
        int i1 = -1; float v1 = -3.0e38f;
        #pragma unroll
        for (int e = 0; e < E; e++) if (e != i0 && nz[e] > v1) { v1 = nz[e]; i1 = e; }

        const float ex = expf(v1 - v0);
        const float inv = 1.f / (1.f + ex);

        const int p0 = atomicAdd(&g_cnt[i0], 1);
        const int p1 = atomicAdd(&g_cnt[i1], 1);
        const int r0 = i0 * T + p0;
        const int r1 = i1 * T + p1;
        g_tok[r0] = warp;
        g_tok[r1] = warp;
        g_rowof[2 * warp]     = r0;
        g_rowof[2 * warp + 1] = r1;
        g_w[2 * warp]     = inv;
        g_w[2 * warp + 1] = ex * inv;
    }
}

// ---------------------------------------------------------------------------
// GEMM helpers
// ---------------------------------------------------------------------------
__device__ __forceinline__ uint32_t smem_u32(const void* p) {
    return (uint32_t)__cvta_generic_to_shared(p);
}
__device__ __forceinline__ void cp16(uint32_t dst, const void* src) {
    asm volatile("cp.async.cg.shared.global [%0], [%1], 16;"
                 :: "r"(dst), "l"(src) : "memory");
}
__device__ __forceinline__ void cp_commit() {
    asm volatile("cp.async.commit_group;" ::: "memory");
}
template <int N>
__device__ __forceinline__ void cp_wait() {
    asm volatile("cp.async.wait_group %0;" :: "n"(N) : "memory");
}
__device__ __forceinline__ void ldsm4(uint32_t& r0, uint32_t& r1, uint32_t& r2, uint32_t& r3,
                                      uint32_t addr) {
    asm volatile("ldmatrix.sync.aligned.m8n8.x4.shared.b16 {%0,%1,%2,%3}, [%4];"
                 : "=r"(r0), "=r"(r1), "=r"(r2), "=r"(r3) : "r"(addr));
}
__device__ __forceinline__ void mma_f16(float& c0, float& c1, float& c2, float& c3,
                                        uint32_t a0, uint32_t a1, uint32_t a2, uint32_t a3,
                                        uint32_t b0, uint32_t b1) {
    asm volatile(
        "mma.sync.aligned.m16n8k16.row.col.f32.f16.f16.f32 "
        "{%0,%1,%2,%3}, {%4,%5,%6,%7}, {%8,%9}, {%0,%1,%2,%3};"
        : "+f"(c0), "+f"(c1), "+f"(c2), "+f"(c3)
        : "r"(a0), "r"(a1), "r"(a2), "r"(a3), "r"(b0), "r"(b1));
}

__device__ __forceinline__ void load_frags(uint32_t (&af)[4][4], uint32_t (&bf)[8][2],
                                           const uint32_t (&aAddr)[4],
                                           const uint32_t (&bAddr)[4], uint32_t off)
{
    #pragma unroll
    for (int mi = 0; mi < 4; mi++)
        ldsm4(af[mi][0], af[mi][1], af[mi][2], af[mi][3], aAddr[mi] + off);
    #pragma unroll
    for (int p = 0; p < 4; p++) {
        uint32_t r0, r1, r2, r3;
        ldsm4(r0, r1, r2, r3, bAddr[p] + off);
        bf[2 * p][0] = r0;     bf[2 * p][1] = r1;
        bf[2 * p + 1][0] = r2; bf[2 * p + 1][1] = r3;
    }
}

__device__ __forceinline__ void mma_tile(float (&acc)[4][8][4],
                                         const uint32_t (&af)[4][4],
                                         const uint32_t (&bf)[8][2])
{
    #pragma unroll
    for (int mi = 0; mi < 4; mi++)
        #pragma unroll
        for (int ni = 0; ni < 8; ni++)
            mma_f16(acc[mi][ni][0], acc[mi][ni][1], acc[mi][ni][2], acc[mi][ni][3],
                    af[mi][0], af[mi][1], af[mi][2], af[mi][3],
                    bf[ni][0], bf[ni][1]);
}

// ---------------------------------------------------------------------------
// Fused persistent GEMM1+GEMM2. One tile queue; ids [0,NT1) are GEMM1 tiles,
// [NT1,NTALL) are GEMM2 tiles. Every GEMM1 tile (incl. skipped) increments
// g_done[e][xi/3]; a GEMM2 tile (e,sK) waits for g_done[e][sK]==48 before its
// prologue. Monotone queue + non-waiting producers => deadlock-free. Values
// and output locations are a pure function of tile id => deterministic.
// ---------------------------------------------------------------------------
__global__ __launch_bounds__(256, 1)
void moe_gemm_fused(const __half* __restrict__ W1h,
                    const __half* __restrict__ W2h,
                    const float* __restrict__ b1,
                    const float* __restrict__ b2)
{
    extern __shared__ __half sm[];
    __shared__ int s_t;

    const int tid  = threadIdx.x;
    const int lane = tid & 31;
    const int warp = tid >> 5;
    const int wm   = warp >> 2;
    const int wn   = warp & 3;
    const int g    = lane >> 2;
    const int q    = lane & 3;

    const int r8 = tid >> 3;
    const int c8 = (tid & 7) * 8;
    const uint32_t smb = smem_u32(sm);
    const uint32_t st0 = smb + (uint32_t)(r8 * SA + c8) * 2;

    uint32_t aAddr[4], bAddr[4];
    {
        const int rin = lane & 15;
        const int ch  = lane >> 4;
        #pragma unroll
        for (int mi = 0; mi < 4; mi++)
            aAddr[mi] = smb + (uint32_t)((wm * 64 + mi * 16 + rin) * SA + ch * 8) * 2;
    }
    {
        const int rin = ((lane >> 4) << 3) + (lane & 7);
        const int ch  = (lane >> 3) & 1;
        #pragma unroll
        for (int p = 0; p < 4; p++)
            bAddr[p] = smb + (uint32_t)((BM + wn * 64 + p * 16 + rin) * SA + ch * 8) * 2;
    }

    for (;;) {
        if (tid == 0) s_t = atomicAdd(&g_q, 1);
        __syncthreads();
        const int t = s_t;
        __syncthreads();
        if (t >= NTALL) break;

        const bool m1 = (t < NT1);
        int xi, yi, e, sK;
        if (m1) {
            xi = t % GX1; yi = (t / GX1) % GY; e = t / (GX1 * GY); sK = 0;
        } else {
            const int t2 = t - NT1;
            xi = t2 % GX2; yi = (t2 / GX2) % GY;
            const int zi = t2 / (GX2 * GY);
            e = zi & (E - 1); sK = zi >> 3;
        }
        const int KROW = m1 ? D : DFF;
        const int NTOT = m1 ? DFF : D;
        const int ks0  = m1 ? 0 : sK * (DFF / SPLITK);

        const int cnt = g_cnt[e];
        const int m0  = yi * BM;
        if (m0 >= cnt) {
            if (m1 && tid == 0) atomicAdd(&g_done[e * SPLITK + xi / 3], 1);
            continue;
        }
        const int n0 = xi * BN;

        // GEMM2 dependency: all 48 GEMM1 tiles covering (e, sK) must be done.
        if (!m1) {
            if (tid == 0) {
                while (atomicAdd(&g_done[e * SPLITK + sK], 0) < DEP_TARGET) {}
            }
            __syncthreads();
        }

        // per-tile source pointers
        const __half* srcA[4];
        #pragma unroll
        for (int k = 0; k < 4; k++) {
            const int am = m0 + r8 + 32 * k;
            if (m1) {
                const int tok = (am < cnt) ? g_tok[e * T + am] : 0;
                srcA[k] = g_xh + (size_t)tok * D + c8;
            } else {
                const int r = (am < cnt) ? am : 0;
                srcA[k] = g_Hh + ((size_t)e * T + r) * DFF + ks0 + c8;
            }
        }
        const __half* Wh = m1 ? W1h : W2h;
        const __half* srcB = Wh + ((size_t)e * NTOT + n0 + r8) * KROW + ks0 + c8;
        const size_t bstep = (size_t)32 * KROW;

        float acc[4][8][4];
        #pragma unroll
        for (int mi = 0; mi < 4; mi++)
            #pragma unroll
            for (int ni = 0; ni < 8; ni++)
                #pragma unroll
                for (int r = 0; r < 4; r++) acc[mi][ni][r] = 0.f;

        auto FILL = [&](int stage, int kt) {
            const uint32_t so = (uint32_t)(stage * STG_BYTES);
            const int ko = kt * BK;
            #pragma unroll
            for (int k = 0; k < 4; k++)
                cp16(st0 + so + k * (32 * SA * 2), srcA[k] + ko);
            #pragma unroll
            for (int k = 0; k < 8; k++)
                cp16(st0 + so + (k + 4) * (32 * SA * 2), srcB + bstep * k + ko);
        };

        #pragma unroll
        for (int s = 0; s < STAGES - 1; s++) { FILL(s, s); cp_commit(); }
        cp_wait<1>();
        __syncthreads();

        uint32_t af0[4][4], bf0[8][2], af1[4][4], bf1[8][2];
        load_frags(af0, bf0, aAddr, bAddr, 0);

        int cur = 0;
        for (int kt = 0; kt < NKT; kt++) {
            const uint32_t soff = (uint32_t)(cur * STG_BYTES);

            load_frags(af1, bf1, aAddr, bAddr, soff + 32);
            if (kt + STAGES - 1 < NKT) {
                int tgt = cur + 2; if (tgt >= STAGES) tgt -= STAGES;
                FILL(tgt, kt + STAGES - 1);
            }
            cp_commit();
            mma_tile(acc, af0, bf0);                       // sub0

            load_frags(af0, bf0, aAddr, bAddr, soff + 64); // sub2 frags
            mma_tile(acc, af1, bf1);                       // sub1

            load_frags(af1, bf1, aAddr, bAddr, soff + 96); // sub3 frags
            mma_tile(acc, af0, bf0);                       // sub2

            cp_wait<1>();
            __syncthreads();

            int nxt = cur + 1; if (nxt >= STAGES) nxt = 0;
            if (kt + 1 < NKT)
                load_frags(af0, bf0, aAddr, bAddr, (uint32_t)(nxt * STG_BYTES));
            mma_tile(acc, af1, bf1);                       // sub3

            cur = nxt;
        }

        // ---- epilogue ----
        if (m1) {
            const float* be = b1 + (size_t)e * DFF;
            __half* Cb = g_Hh + (size_t)e * T * DFF;
            #pragma unroll
            for (int mi = 0; mi < 4; mi++) {
                #pragma unroll
                for (int hh = 0; hh < 2; hh++) {
                    const int m = m0 + wm * 64 + mi * 16 + g + hh * 8;
                    if (m < cnt) {
                        __half* cr = Cb + (size_t)m * DFF;
                        #pragma unroll
                        for (int ni = 0; ni < 8; ni++) {
                            const int c = n0 + wn * 64 + ni * 8 + 2 * q;
                            float v0 = acc[mi][ni][2 * hh]     + be[c];
                            float v1 = acc[mi][ni][2 * hh + 1] + be[c + 1];
                            v0 = fmaxf(v0, 0.f); v1 = fmaxf(v1, 0.f);
                            *reinterpret_cast<__half2*>(cr + c) = __floats2half2_rn(v0, v1);
                        }
                    }
                }
            }
            // publish: all threads fence own stores, then one arrive
            __threadfence();
            __syncthreads();
            if (tid == 0) atomicAdd(&g_done[e * SPLITK + xi / 3], 1);
        } else {
            const float* be = b2 + (size_t)e * D;
            float* Cb = g_Y[sK] + (size_t)e * T * D;
            #pragma unroll
            for (int mi = 0; mi < 4; mi++) {
                #pragma unroll
                for (int hh = 0; hh < 2; hh++) {
                    const int m = m0 + wm * 64 + mi * 16 + g + hh * 8;
                    if (m < cnt) {
                        float* cr = Cb + (size_t)m * D;
                        #pragma unroll
                        for (int ni = 0; ni < 8; ni++) {
                            const int c = n0 + wn * 64 + ni * 8 + 2 * q;
                            float v0 = acc[mi][ni][2 * hh];
                            float v1 = acc[mi][ni][2 * hh + 1];
                            if (sK == 0) { v0 += be[c]; v1 += be[c + 1]; }
                            *reinterpret_cast<float2*>(cr + c) = make_float2(v0, v1);
                        }
                    }
                }
            }
        }
    }
}

// ---------------------------------------------------------------------------
// Combine (deterministic): out[t] = w0*sum_s Ys[r0] + w1*sum_s Ys[r1]
// ---------------------------------------------------------------------------
__global__ void combine_kernel(float* __restrict__ out)
{
    const int t = blockIdx.x;
    const int j = threadIdx.x;            // 0..191
    const int r0 = g_rowof[2 * t];
    const int r1 = g_rowof[2 * t + 1];
    const float w0 = g_w[2 * t];
    const float w1 = g_w[2 * t + 1];
    float4 sa = make_float4(0.f, 0.f, 0.f, 0.f);
    float4 sb = make_float4(0.f, 0.f, 0.f, 0.f);
    #pragma unroll
    for (int s = 0; s < SPLITK; s++) {
        const float4 a = reinterpret_cast<const float4*>(g_Y[s] + (size_t)r0 * D)[j];
        const float4 b = reinterpret_cast<const float4*>(g_Y[s] + (size_t)r1 * D)[j];
        sa.x += a.x; sa.y += a.y; sa.z += a.z; sa.w += a.w;
        sb.x += b.x; sb.y += b.y; sb.z += b.z; sb.w += b.w;
    }
    float4 o;
    o.x = fmaf(w0, sa.x, w1 * sb.x);
    o.y = fmaf(w0, sa.y, w1 * sb.y);
    o.z = fmaf(w0, sa.z, w1 * sb.z);
    o.w = fmaf(w0, sa.w, w1 * sb.w);
    reinterpret_cast<float4*>(out + (size_t)t * D)[j] = o;
}

// ---------------------------------------------------------------------------
// Launch
// ---------------------------------------------------------------------------
extern "C" void kernel_launch(void* const* d_in, const int* in_sizes, int n_in,
                              void* d_out, int out_size)
{
    const float* x     = (const float*)d_in[0];
    const float* noise = (const float*)d_in[1];
    const float* Wg    = (const float*)d_in[2];
    const float* bg    = (const float*)d_in[3];
    const float* Wn    = (const float*)d_in[4];
    const float* bn    = (const float*)d_in[5];
    const float* W1    = (const float*)d_in[6];
    const float* b1    = (const float*)d_in[7];
    const float* W2    = (const float*)d_in[8];
    const float* b2    = (const float*)d_in[9];
    float* out = (float*)d_out;

    cudaFuncSetAttribute(moe_gemm_fused,
                         cudaFuncAttributeMaxDynamicSharedMemorySize, SMEM_TOT);

    reset_kernel<<<1, 64>>>();

    // fp32 -> fp16 conversions (x, W1, W2) in one launch
    __half* xh;  cudaGetSymbolAddress((void**)&xh,  g_xh);
    __half* w1h; cudaGetSymbolAddress((void**)&w1h, g_W1h);
    __half* w2h; cudaGetSymbolAddress((void**)&w2h, g_W2h);
    {
        const int nx8 = T * D / 8;
        const int nw8 = E * DFF * D / 8;
        const int tot = nx8 + 2 * nw8;
        cvt3_kernel<<<(tot + 255) / 256, 256>>>(x, W1, W2, xh, w1h, w2h, nx8, nw8);
    }

    router_kernel<<<T / 8, 256>>>(x, noise, Wg, bg, Wn, bn);

    // fused persistent GEMM1+GEMM2
    moe_gemm_fused<<<NSM, 256, SMEM_TOT>>>(w1h, w2h, b1, b2);

    combine_kernel<<<T, D / 4>>>(out);
}